// round 1
// baseline (speedup 1.0000x reference)
#include <cuda_runtime.h>
#include <math.h>

#define T_  4
#define B_  16
#define CIN 3
#define HIMG 64
#define WIMG 64
#define NN  6
#define COUT 128
#define HP  32
#define WPx 32
#define NH  4
#define HDm 32
#define BN_EPS 1e-5f
#define V_TH 1.0f

// ---------------- persistent device state ----------------
__device__ float g_v0[B_*COUT*HIMG*WIMG];           // PLIF state node 0 (64x64)
__device__ float g_vnodes[(NN-1)*B_*COUT*HP*WPx];   // PLIF state nodes 1..5 (32x32)
__device__ float g_traces[B_*NN*COUT];
__device__ float g_out0[B_*COUT*HP*WPx];            // pooled spikes of node 0 (this t)
__device__ float g_mean0[B_*COUT];                  // spatial mean of out0
__device__ float g_feat0[B_*COUT];
__device__ float g_nodemean[(NN-1)*B_*COUT];        // spike means nodes 1..5
__device__ float g_c[B_*NN];                        // diffusion coefficients (op^2)[:, :, 0]

// ---------------- init: zero state ----------------
__global__ void k_init() {
    long long idx = (long long)blockIdx.x * blockDim.x + threadIdx.x;
    long long stride = (long long)gridDim.x * blockDim.x;
    for (long long i = idx; i < (long long)B_*COUT*HIMG*WIMG; i += stride) g_v0[i] = 0.f;
    for (long long i = idx; i < (long long)(NN-1)*B_*COUT*HP*WPx; i += stride) g_vnodes[i] = 0.f;
    for (long long i = idx; i < B_*NN*COUT; i += stride) g_traces[i] = 0.f;
    for (long long i = idx; i < B_*COUT; i += stride) g_mean0[i] = 0.f;
}

// ---------------- K1: conv0 + bn0 + plif0 + spike + 2x2 pool ----------------
// grid (32, B): bx -> cog(0..15), half(0..1).  256 threads.
__global__ __launch_bounds__(256)
void k1_conv0(const float* __restrict__ x_t, const float* __restrict__ w0,
              const float* __restrict__ bg, const float* __restrict__ bb,
              const float* __restrict__ bm, const float* __restrict__ bv,
              const float* __restrict__ plifw, const float* __restrict__ outw,
              float* __restrict__ out_t)
{
    const int bx = blockIdx.x;
    const int cog = bx >> 1;      // 16 groups of 8 co
    const int half = bx & 1;      // top/bottom half of image
    const int b = blockIdx.y;
    const int tid = threadIdx.x;

    __shared__ __align__(16) float s_x[CIN*34*68];
    __shared__ float s_w[8*27];
    __shared__ float s_sum[8];

    if (tid < 8) s_sum[tid] = 0.f;
    if (tid < 216) s_w[tid] = w0[cog*216 + tid];

    // stage input rows [half*32-1, half*32+32] x cols [-1,64] (zero padded)
    for (int idx = tid; idx < CIN*34*66; idx += 256) {
        int ci = idx / (34*66);
        int rem = idx % (34*66);
        int y = rem / 66, xc = rem % 66;
        int gy = half*32 - 1 + y, gx = xc - 1;
        float v = 0.f;
        if (gy >= 0 && gy < HIMG && gx >= 0 && gx < WIMG)
            v = x_t[(b*CIN + ci)*HIMG*WIMG + gy*WIMG + gx];
        s_x[(ci*34 + y)*68 + xc] = v;
    }

    float bnA[8], bnB[8];
    #pragma unroll
    for (int co = 0; co < 8; ++co) {
        int cg_ = cog*8 + co;
        float inv = rsqrtf(bv[cg_] + BN_EPS);
        bnA[co] = bg[cg_] * inv;
        bnB[co] = bb[cg_] - bm[cg_] * bnA[co];
    }
    const float sig0 = 1.f / (1.f + expf(-plifw[0]));
    const float ws0  = 1.f / (1.f + expf(-outw[0]));

    __syncthreads();

    float lsum[8];
    #pragma unroll
    for (int co = 0; co < 8; ++co) lsum[co] = 0.f;

    #pragma unroll
    for (int q = 0; q < 2; ++q) {
        int p = tid + 256*q;           // pooled pixel within this half (512 of them)
        int php = p >> 5, pwp = p & 31;
        int hp = half*16 + php;
        int wp = pwp;
        int ty0 = php*2, tx0 = pwp*2;  // halo-tile coords of 4x4 window

        float xin[CIN][4][4];
        #pragma unroll
        for (int ci = 0; ci < CIN; ++ci)
            #pragma unroll
            for (int r = 0; r < 4; ++r)
                #pragma unroll
                for (int c = 0; c < 4; ++c)
                    xin[ci][r][c] = s_x[(ci*34 + ty0 + r)*68 + tx0 + c];

        #pragma unroll
        for (int co = 0; co < 8; ++co) {
            float s00=0.f, s01=0.f, s10=0.f, s11=0.f;
            #pragma unroll
            for (int ci = 0; ci < CIN; ++ci) {
                #pragma unroll
                for (int kh = 0; kh < 3; ++kh)
                    #pragma unroll
                    for (int kw = 0; kw < 3; ++kw) {
                        float wv = s_w[co*27 + ci*9 + kh*3 + kw];
                        s00 = fmaf(xin[ci][kh  ][kw  ], wv, s00);
                        s01 = fmaf(xin[ci][kh  ][kw+1], wv, s01);
                        s10 = fmaf(xin[ci][kh+1][kw  ], wv, s10);
                        s11 = fmaf(xin[ci][kh+1][kw+1], wv, s11);
                    }
            }
            int cg_ = cog*8 + co;
            long long vbase = ((long long)(b*COUT + cg_)*HIMG + hp*2)*WIMG + wp*2;
            float spsum = 0.f;
            float convs4[4] = {s00, s01, s10, s11};
            long long voff[4] = {0, 1, WIMG, WIMG+1};
            #pragma unroll
            for (int e = 0; e < 4; ++e) {
                float xc = convs4[e]*bnA[co] + bnB[co];
                long long vi = vbase + voff[e];
                float vp = g_v0[vi];
                float v = vp + (xc - vp)*sig0;
                float sk = (v >= V_TH) ? 1.f : 0.f;
                g_v0[vi] = v * (1.f - sk);
                spsum += sk;
            }
            float pooled = spsum * 0.25f;
            int oidx = (b*COUT + cg_)*HP*WPx + hp*WPx + wp;
            g_out0[oidx] = pooled;
            out_t[oidx] = ws0 * pooled;     // node-0 contribution (plain store)
            lsum[co] += pooled;
        }
    }

    // warp reduce then block reduce spatial sums
    #pragma unroll
    for (int co = 0; co < 8; ++co) {
        float v = lsum[co];
        #pragma unroll
        for (int off = 16; off > 0; off >>= 1)
            v += __shfl_down_sync(0xffffffffu, v, off);
        if ((tid & 31) == 0) atomicAdd(&s_sum[co], v);
    }
    __syncthreads();
    if (tid < 8)
        atomicAdd(&g_mean0[b*COUT + cog*8 + tid], s_sum[tid] * (1.f/1024.f));
}

// ---------------- K2: feat0, trace row0 update, GAT -> softmax -> topk -> diffusion -> c ----------------
// grid (B), 128 threads
__global__ __launch_bounds__(128)
void k2_graph(const float* __restrict__ ft_w, const float* __restrict__ ft_b,
              const float* __restrict__ gat_W, const float* __restrict__ gat_a)
{
    const int b = blockIdx.x;
    const int tid = threadIdx.x;

    __shared__ float s_tr[NN][COUT];
    __shared__ float s_m0[COUT];
    __shared__ float s_hp[NN][COUT];
    __shared__ float s_e1[NN*NH], s_e2[NN*NH];
    __shared__ float s_attn[NN*NN];
    __shared__ float s_S[NN*NN];
    __shared__ float s_Sp[NN*NN];
    __shared__ float s_adj[NN*NN];
    __shared__ float s_dis[NN];
    __shared__ float s_op[NN*NN];

    s_m0[tid] = g_mean0[b*COUT + tid];
    #pragma unroll
    for (int n = 0; n < NN; ++n)
        s_tr[n][tid] = g_traces[(b*NN + n)*COUT + tid];
    __syncthreads();

    // feat0 = relu(mean0 @ ft_w.T + ft_b)
    {
        float acc = ft_b[tid];
        #pragma unroll 4
        for (int c = 0; c < COUT; ++c)
            acc = fmaf(s_m0[c], ft_w[tid*COUT + c], acc);
        float f0 = fmaxf(acc, 0.f);
        g_feat0[b*COUT + tid] = f0;
        float t0 = 0.6f * s_tr[0][tid] + 0.4f * f0;
        s_tr[0][tid] = t0;
        g_traces[(b*NN + 0)*COUT + tid] = t0;
    }
    __syncthreads();

    // hp = traces @ gat_W.T   (6x128)
    for (int e = tid; e < NN*COUT; e += 128) {
        int n = e >> 7, r = e & 127;
        float acc = 0.f;
        #pragma unroll 4
        for (int c = 0; c < COUT; ++c)
            acc = fmaf(s_tr[n][c], gat_W[r*COUT + c], acc);
        s_hp[n][r] = acc;
    }
    __syncthreads();

    if (tid < NN*NH) {
        int n = tid >> 2, h = tid & 3;
        float a1 = 0.f, a2 = 0.f;
        #pragma unroll
        for (int d = 0; d < HDm; ++d) {
            float v = s_hp[n][h*HDm + d];
            a1 = fmaf(v, gat_a[h*2*HDm + d], a1);
            a2 = fmaf(v, gat_a[h*2*HDm + HDm + d], a2);
        }
        s_e1[tid] = a1; s_e2[tid] = a2;
    }
    __syncthreads();

    if (tid < NN*NN) {
        int i = tid / NN, j = tid % NN;
        float s = 0.f;
        #pragma unroll
        for (int h = 0; h < NH; ++h) {
            float v1 = s_e1[i*NH + h] + s_e2[j*NH + h];
            v1 = (v1 > 0.f) ? v1 : 0.2f * v1;
            float v2 = s_e1[j*NH + h] + s_e2[i*NH + h];
            v2 = (v2 > 0.f) ? v2 : 0.2f * v2;
            s += 0.5f * (v1 + v2);
        }
        s_attn[tid] = s * (1.f / NH);
    }
    __syncthreads();

    if (tid < NN) {
        // softmax(attn/0.01) over row
        float z[NN], m = -1e30f;
        #pragma unroll
        for (int j = 0; j < NN; ++j) { z[j] = s_attn[tid*NN + j] * 100.f; m = fmaxf(m, z[j]); }
        float ssum = 0.f;
        #pragma unroll
        for (int j = 0; j < NN; ++j) { z[j] = expf(z[j] - m); ssum += z[j]; }
        float inv = 1.f / ssum;
        float v[NN];
        #pragma unroll
        for (int j = 0; j < NN; ++j) { v[j] = z[j] * inv; s_S[tid*NN + j] = v[j]; }
        // 3rd largest (with multiplicity)
        float m1 = -1.f, m2 = -1.f, m3 = -1.f;
        #pragma unroll
        for (int j = 0; j < NN; ++j) {
            float x = v[j];
            if (x > m1) { m3 = m2; m2 = m1; m1 = x; }
            else if (x > m2) { m3 = m2; m2 = x; }
            else if (x > m3) { m3 = x; }
        }
        #pragma unroll
        for (int j = 0; j < NN; ++j)
            s_Sp[tid*NN + j] = (v[j] >= m3) ? v[j] : 0.f;
    }
    __syncthreads();

    if (tid < NN*NN) {
        int i = tid / NN, j = tid % NN;
        s_adj[tid] = 0.5f * (s_Sp[i*NN + j] + s_Sp[j*NN + i]);
    }
    __syncthreads();

    if (tid < NN) {
        float d = 0.f;
        #pragma unroll
        for (int j = 0; j < NN; ++j) d += s_adj[tid*NN + j];
        s_dis[tid] = 1.f / sqrtf(d + 1e-6f);
    }
    __syncthreads();

    if (tid < NN*NN) {
        int i = tid / NN, j = tid % NN;
        s_op[tid] = s_dis[i] * s_adj[tid] * s_dis[j];
    }
    __syncthreads();

    if (tid < NN) {
        float c = 0.f;
        #pragma unroll
        for (int j = 0; j < NN; ++j)
            c = fmaf(s_op[tid*NN + j], s_op[j*NN + 0], c);
        g_c[b*NN + tid] = c;
    }
}

// ---------------- K3: node convs (hot kernel) ----------------
// conv(c*out0, w_i) = c * conv(out0, w_i). Fused bn+plif+spike+output+spike-mean.
// grid (8 cogroups, 5 nodes, B).  256 threads: (cg 0..3) x (64 spatial 4x4 tiles)
__global__ __launch_bounds__(256)
void k3_nodes(const float* __restrict__ convs_w,
              const float* __restrict__ bg, const float* __restrict__ bb,
              const float* __restrict__ bm, const float* __restrict__ bv,
              const float* __restrict__ plifw, const float* __restrict__ outw,
              float* __restrict__ out_t)
{
    const int cog  = blockIdx.x;       // 0..7 -> 16 output channels
    const int node = blockIdx.y + 1;   // 1..5
    const int b    = blockIdx.z;
    const int tid  = threadIdx.x;
    const int sp   = tid & 63;
    const int cg   = tid >> 6;         // 0..3 -> 4 channels each
    const int tr   = sp >> 3, tc = sp & 7;
    const int hp0  = tr * 4, wp0 = tc * 4;
    const int coBase = cog * 16 + cg * 4;

    __shared__ __align__(16) float s_in[4][34][36];
    __shared__ __align__(16) float s_w[4][16][12];
    __shared__ float s_red[16];

    if (tid < 16) s_red[tid] = 0.f;

    float acc[4][16];
    #pragma unroll
    for (int u = 0; u < 4; ++u)
        #pragma unroll
        for (int p = 0; p < 16; ++p) acc[u][p] = 0.f;

    const float* inbase = g_out0 + (long long)b*COUT*HP*WPx;
    const float* wbase  = convs_w + ((long long)(node-1)*COUT + cog*16)*COUT*9;

    for (int ci0 = 0; ci0 < COUT; ci0 += 4) {
        __syncthreads();
        // stage 4 input planes with halo (zero padded), row stride 36
        for (int idx = tid; idx < 4*34*36; idx += 256) {
            int cc = idx / (34*36);
            int rem = idx % (34*36);
            int y = rem / 36, xcol = rem % 36;
            float v = 0.f;
            int gy = y - 1, gx = xcol - 1;
            if (xcol < 34 && gy >= 0 && gy < HP && gx >= 0 && gx < WPx)
                v = inbase[(ci0 + cc)*HP*WPx + gy*WPx + gx];
            s_in[cc][y][xcol] = v;
        }
        // stage weights: [cc][co(16)][12] (9 used)
        for (int idx = tid; idx < 4*16*12; idx += 256) {
            int cc = idx / 192;
            int rem = idx % 192;
            int co = rem / 12, k = rem % 12;
            s_w[cc][co][k] = (k < 9) ? wbase[(long long)co*COUT*9 + (ci0 + cc)*9 + k] : 0.f;
        }
        __syncthreads();

        #pragma unroll
        for (int cc = 0; cc < 4; ++cc) {
            float xin[6][6];
            #pragma unroll
            for (int r = 0; r < 6; ++r) {
                const float* rp = &s_in[cc][hp0 + r][wp0];
                float4 v4 = *reinterpret_cast<const float4*>(rp);
                float2 v2 = *reinterpret_cast<const float2*>(rp + 4);
                xin[r][0] = v4.x; xin[r][1] = v4.y; xin[r][2] = v4.z; xin[r][3] = v4.w;
                xin[r][4] = v2.x; xin[r][5] = v2.y;
            }
            #pragma unroll
            for (int u = 0; u < 4; ++u) {
                const float* wp_ = &s_w[cc][cg*4 + u][0];
                float4 wa = *reinterpret_cast<const float4*>(wp_);
                float4 wb = *reinterpret_cast<const float4*>(wp_ + 4);
                float w8 = wp_[8];
                float w_[9] = {wa.x, wa.y, wa.z, wa.w, wb.x, wb.y, wb.z, wb.w, w8};
                #pragma unroll
                for (int ph = 0; ph < 4; ++ph)
                    #pragma unroll
                    for (int pw = 0; pw < 4; ++pw) {
                        float a = acc[u][ph*4 + pw];
                        #pragma unroll
                        for (int kh = 0; kh < 3; ++kh)
                            #pragma unroll
                            for (int kw = 0; kw < 3; ++kw)
                                a = fmaf(xin[ph + kh][pw + kw], w_[kh*3 + kw], a);
                        acc[u][ph*4 + pw] = a;
                    }
            }
        }
    }

    // epilogue
    const float cscale = g_c[b*NN + node];
    const float sig = 1.f / (1.f + expf(-plifw[node]));
    const float ws  = 1.f / (1.f + expf(-outw[node]));

    #pragma unroll
    for (int u = 0; u < 4; ++u) {
        int co = coBase + u;
        int bi = (node - 1)*COUT + co;
        float inv = rsqrtf(bv[bi] + BN_EPS);
        float A = bg[bi] * inv;
        float Bc = bb[bi] - bm[bi] * A;
        float lsum = 0.f;
        #pragma unroll
        for (int p = 0; p < 16; ++p) {
            int ph = p >> 2, pw = p & 3;
            float y = acc[u][p] * cscale;
            float ybn = y * A + Bc;
            long long vi = (((long long)(node-1)*B_ + b)*COUT + co)*HP*WPx
                         + (hp0 + ph)*WPx + (wp0 + pw);
            float vp = g_vnodes[vi];
            float v = vp + (ybn - vp)*sig;
            float sk = (v >= V_TH) ? 1.f : 0.f;
            g_vnodes[vi] = v * (1.f - sk);
            atomicAdd(&out_t[(b*COUT + co)*HP*WPx + (hp0 + ph)*WPx + (wp0 + pw)], ws * sk);
            lsum += sk;
        }
        atomicAdd(&s_red[cg*4 + u], lsum);
    }
    __syncthreads();
    if (tid < 16)
        g_nodemean[((node-1)*B_ + b)*COUT + cog*16 + tid] = s_red[tid] * (1.f/1024.f);
}

// ---------------- K4: node feats -> trace decay update; zero mean0 for next t ----------------
// grid (B), 128 threads
__global__ __launch_bounds__(128)
void k4_feats(const float* __restrict__ ft_w, const float* __restrict__ ft_b)
{
    const int b = blockIdx.x;
    const int tid = threadIdx.x;
    __shared__ float s_m[COUT];

    float f[NN];
    f[0] = g_feat0[b*COUT + tid];
    for (int n = 1; n < NN; ++n) {
        __syncthreads();
        s_m[tid] = g_nodemean[((n-1)*B_ + b)*COUT + tid];
        __syncthreads();
        float acc = ft_b[tid];
        #pragma unroll 4
        for (int c = 0; c < COUT; ++c)
            acc = fmaf(s_m[c], ft_w[tid*COUT + c], acc);
        f[n] = fmaxf(acc, 0.f);
    }
    #pragma unroll
    for (int n = 0; n < NN; ++n) {
        int idx = (b*NN + n)*COUT + tid;
        g_traces[idx] = 0.6f * g_traces[idx] + 0.4f * f[n];
    }
    g_mean0[b*COUT + tid] = 0.f;   // for next time step's K1 atomics
}

// ---------------- host launch ----------------
extern "C" void kernel_launch(void* const* d_in, const int* in_sizes, int n_in,
                              void* d_out, int out_size)
{
    const float* x       = (const float*)d_in[0];
    const float* conv0_w = (const float*)d_in[1];
    const float* bn0_g   = (const float*)d_in[2];
    const float* bn0_b   = (const float*)d_in[3];
    const float* bn0_m   = (const float*)d_in[4];
    const float* bn0_v   = (const float*)d_in[5];
    const float* convs_w = (const float*)d_in[6];
    const float* bns_g   = (const float*)d_in[7];
    const float* bns_b   = (const float*)d_in[8];
    const float* bns_m   = (const float*)d_in[9];
    const float* bns_v   = (const float*)d_in[10];
    const float* plif_w  = (const float*)d_in[11];
    const float* ft_w    = (const float*)d_in[12];
    const float* ft_b    = (const float*)d_in[13];
    const float* gat_W   = (const float*)d_in[14];
    const float* gat_a   = (const float*)d_in[15];
    const float* out_w   = (const float*)d_in[16];
    float* out = (float*)d_out;

    k_init<<<2048, 256>>>();

    for (int t = 0; t < T_; ++t) {
        const float* xt = x + (long long)t * B_ * CIN * HIMG * WIMG;
        float* out_t = out + (long long)t * B_ * COUT * HP * WPx;

        k1_conv0<<<dim3(32, B_), 256>>>(xt, conv0_w, bn0_g, bn0_b, bn0_m, bn0_v,
                                        plif_w, out_w, out_t);
        k2_graph<<<B_, 128>>>(ft_w, ft_b, gat_W, gat_a);
        k3_nodes<<<dim3(8, NN-1, B_), 256>>>(convs_w, bns_g, bns_b, bns_m, bns_v,
                                             plif_w, out_w, out_t);
        k4_feats<<<B_, 128>>>(ft_w, ft_b);
    }
}

// round 2
// speedup vs baseline: 1.2780x; 1.2780x over previous
#include <cuda_runtime.h>
#include <math.h>

#define T_  4
#define B_  16
#define CIN 3
#define HIMG 64
#define WIMG 64
#define NN  6
#define COUT 128
#define HP  32
#define WPx 32
#define NH  4
#define HDm 32
#define BN_EPS 1e-5f
#define V_TH 1.0f

#define PLANE (HP*WPx)            // 1024
#define OUTSZ (B_*COUT*PLANE)     // per-timestep output elements

typedef unsigned long long u64;

__device__ __forceinline__ u64 bcast2(float v) {
    u64 r; asm("mov.b64 %0, {%1,%1};" : "=l"(r) : "f"(v)); return r;
}
__device__ __forceinline__ void ffma2(u64 &d, u64 a, u64 b) {
    asm("fma.rn.f32x2 %0, %1, %2, %0;" : "+l"(d) : "l"(a), "l"(b));
}
__device__ __forceinline__ void unpack2(float &lo, float &hi, u64 v) {
    asm("mov.b64 {%0,%1}, %2;" : "=f"(lo), "=f"(hi) : "l"(v));
}

// ---------------- persistent device state ----------------
__device__ float g_v0[B_*COUT*HIMG*WIMG];             // PLIF state node 0 (64x64)
__device__ float g_vnodes[(NN-1)*B_*COUT*PLANE];      // PLIF state nodes 1..5
__device__ float g_traces[B_*NN*COUT];
__device__ __align__(16) float g_out0p[B_*COUT*34*36];// pooled node-0 spikes, padded halo
__device__ float g_mean0[B_*COUT];
__device__ float g_feat0[B_*COUT];
__device__ float g_nodemean[(NN-1)*B_*COUT];
__device__ float g_c[B_*NN];                          // diffusion coefficients
__device__ __align__(16) float g_wt[(NN-1)*COUT*9*COUT]; // weights [n][ci][k][co]
__device__ float g_spk[(NN-1)*OUTSZ];                 // raw spikes nodes 1..5

// ---------------- init: zero state (borders of g_out0p stay 0 forever) ----------------
__global__ void k_init() {
    long long idx = (long long)blockIdx.x * blockDim.x + threadIdx.x;
    long long stride = (long long)gridDim.x * blockDim.x;
    for (long long i = idx; i < (long long)B_*COUT*HIMG*WIMG; i += stride) g_v0[i] = 0.f;
    for (long long i = idx; i < (long long)(NN-1)*B_*COUT*PLANE; i += stride) g_vnodes[i] = 0.f;
    for (long long i = idx; i < (long long)B_*COUT*34*36; i += stride) g_out0p[i] = 0.f;
    for (long long i = idx; i < B_*NN*COUT; i += stride) g_traces[i] = 0.f;
    for (long long i = idx; i < B_*COUT; i += stride) g_mean0[i] = 0.f;
}

// ---------------- weight reorg: [n][co][ci][3][3] -> [n][ci][k][co] ----------------
__global__ void k_wreorg(const float* __restrict__ convs_w) {
    int idx = blockIdx.x * blockDim.x + threadIdx.x;   // over n,ci,k,co
    if (idx >= (NN-1)*COUT*9*COUT) return;
    int co = idx % COUT; int t = idx / COUT;
    int k = t % 9; t /= 9;
    int ci = t % COUT; int n = t / COUT;
    g_wt[idx] = convs_w[(((long long)n*COUT + co)*COUT + ci)*9 + k];
}

// ---------------- K1: conv0 + bn0 + plif0 + spike + 2x2 pool ----------------
__global__ __launch_bounds__(256)
void k1_conv0(const float* __restrict__ x_t, const float* __restrict__ w0,
              const float* __restrict__ bg, const float* __restrict__ bb,
              const float* __restrict__ bm, const float* __restrict__ bv,
              const float* __restrict__ plifw, const float* __restrict__ outw,
              float* __restrict__ out_t)
{
    const int bx = blockIdx.x;
    const int cog = bx >> 1;      // 16 groups of 8 co
    const int half = bx & 1;
    const int b = blockIdx.y;
    const int tid = threadIdx.x;

    __shared__ __align__(16) float s_x[CIN*34*68];
    __shared__ float s_w[8*27];
    __shared__ float s_sum[8];

    if (tid < 8) s_sum[tid] = 0.f;
    if (tid < 216) s_w[tid] = w0[cog*216 + tid];

    for (int idx = tid; idx < CIN*34*66; idx += 256) {
        int ci = idx / (34*66);
        int rem = idx % (34*66);
        int y = rem / 66, xc = rem % 66;
        int gy = half*32 - 1 + y, gx = xc - 1;
        float v = 0.f;
        if (gy >= 0 && gy < HIMG && gx >= 0 && gx < WIMG)
            v = x_t[(b*CIN + ci)*HIMG*WIMG + gy*WIMG + gx];
        s_x[(ci*34 + y)*68 + xc] = v;
    }

    float bnA[8], bnB[8];
    #pragma unroll
    for (int co = 0; co < 8; ++co) {
        int cg_ = cog*8 + co;
        float inv = rsqrtf(bv[cg_] + BN_EPS);
        bnA[co] = bg[cg_] * inv;
        bnB[co] = bb[cg_] - bm[cg_] * bnA[co];
    }
    const float sig0 = 1.f / (1.f + expf(-plifw[0]));
    const float ws0  = 1.f / (1.f + expf(-outw[0]));

    __syncthreads();

    float lsum[8];
    #pragma unroll
    for (int co = 0; co < 8; ++co) lsum[co] = 0.f;

    #pragma unroll
    for (int q = 0; q < 2; ++q) {
        int p = tid + 256*q;
        int php = p >> 5, pwp = p & 31;
        int hp = half*16 + php;
        int wp = pwp;
        int ty0 = php*2, tx0 = pwp*2;

        float xin[CIN][4][4];
        #pragma unroll
        for (int ci = 0; ci < CIN; ++ci)
            #pragma unroll
            for (int r = 0; r < 4; ++r)
                #pragma unroll
                for (int c = 0; c < 4; ++c)
                    xin[ci][r][c] = s_x[(ci*34 + ty0 + r)*68 + tx0 + c];

        #pragma unroll
        for (int co = 0; co < 8; ++co) {
            float s00=0.f, s01=0.f, s10=0.f, s11=0.f;
            #pragma unroll
            for (int ci = 0; ci < CIN; ++ci) {
                #pragma unroll
                for (int kh = 0; kh < 3; ++kh)
                    #pragma unroll
                    for (int kw = 0; kw < 3; ++kw) {
                        float wv = s_w[co*27 + ci*9 + kh*3 + kw];
                        s00 = fmaf(xin[ci][kh  ][kw  ], wv, s00);
                        s01 = fmaf(xin[ci][kh  ][kw+1], wv, s01);
                        s10 = fmaf(xin[ci][kh+1][kw  ], wv, s10);
                        s11 = fmaf(xin[ci][kh+1][kw+1], wv, s11);
                    }
            }
            int cg_ = cog*8 + co;
            long long vbase = ((long long)(b*COUT + cg_)*HIMG + hp*2)*WIMG + wp*2;
            float spsum = 0.f;
            float convs4[4] = {s00, s01, s10, s11};
            long long voff[4] = {0, 1, WIMG, WIMG+1};
            #pragma unroll
            for (int e = 0; e < 4; ++e) {
                float xc = convs4[e]*bnA[co] + bnB[co];
                long long vi = vbase + voff[e];
                float vp = g_v0[vi];
                float v = vp + (xc - vp)*sig0;
                float sk = (v >= V_TH) ? 1.f : 0.f;
                g_v0[vi] = v * (1.f - sk);
                spsum += sk;
            }
            float pooled = spsum * 0.25f;
            // padded layout for K3 staging
            g_out0p[((b*COUT + cg_)*34 + hp + 1)*36 + (wp + 1)] = pooled;
            out_t[(b*COUT + cg_)*PLANE + hp*WPx + wp] = ws0 * pooled;
            lsum[co] += pooled;
        }
    }

    #pragma unroll
    for (int co = 0; co < 8; ++co) {
        float v = lsum[co];
        #pragma unroll
        for (int off = 16; off > 0; off >>= 1)
            v += __shfl_down_sync(0xffffffffu, v, off);
        if ((tid & 31) == 0) atomicAdd(&s_sum[co], v);
    }
    __syncthreads();
    if (tid < 8)
        atomicAdd(&g_mean0[b*COUT + cog*8 + tid], s_sum[tid] * (1.f/1024.f));
}

// ---------------- K2: graph machinery (unchanged) ----------------
__global__ __launch_bounds__(128)
void k2_graph(const float* __restrict__ ft_w, const float* __restrict__ ft_b,
              const float* __restrict__ gat_W, const float* __restrict__ gat_a)
{
    const int b = blockIdx.x;
    const int tid = threadIdx.x;

    __shared__ float s_tr[NN][COUT];
    __shared__ float s_m0[COUT];
    __shared__ float s_hp[NN][COUT];
    __shared__ float s_e1[NN*NH], s_e2[NN*NH];
    __shared__ float s_attn[NN*NN];
    __shared__ float s_Sp[NN*NN];
    __shared__ float s_adj[NN*NN];
    __shared__ float s_dis[NN];
    __shared__ float s_op[NN*NN];

    s_m0[tid] = g_mean0[b*COUT + tid];
    #pragma unroll
    for (int n = 0; n < NN; ++n)
        s_tr[n][tid] = g_traces[(b*NN + n)*COUT + tid];
    __syncthreads();

    {
        float acc = ft_b[tid];
        #pragma unroll 4
        for (int c = 0; c < COUT; ++c)
            acc = fmaf(s_m0[c], ft_w[tid*COUT + c], acc);
        float f0 = fmaxf(acc, 0.f);
        g_feat0[b*COUT + tid] = f0;
        float t0 = 0.6f * s_tr[0][tid] + 0.4f * f0;
        s_tr[0][tid] = t0;
        g_traces[(b*NN + 0)*COUT + tid] = t0;
    }
    __syncthreads();

    for (int e = tid; e < NN*COUT; e += 128) {
        int n = e >> 7, r = e & 127;
        float acc = 0.f;
        #pragma unroll 4
        for (int c = 0; c < COUT; ++c)
            acc = fmaf(s_tr[n][c], gat_W[r*COUT + c], acc);
        s_hp[n][r] = acc;
    }
    __syncthreads();

    if (tid < NN*NH) {
        int n = tid >> 2, h = tid & 3;
        float a1 = 0.f, a2 = 0.f;
        #pragma unroll
        for (int d = 0; d < HDm; ++d) {
            float v = s_hp[n][h*HDm + d];
            a1 = fmaf(v, gat_a[h*2*HDm + d], a1);
            a2 = fmaf(v, gat_a[h*2*HDm + HDm + d], a2);
        }
        s_e1[tid] = a1; s_e2[tid] = a2;
    }
    __syncthreads();

    if (tid < NN*NN) {
        int i = tid / NN, j = tid % NN;
        float s = 0.f;
        #pragma unroll
        for (int h = 0; h < NH; ++h) {
            float v1 = s_e1[i*NH + h] + s_e2[j*NH + h];
            v1 = (v1 > 0.f) ? v1 : 0.2f * v1;
            float v2 = s_e1[j*NH + h] + s_e2[i*NH + h];
            v2 = (v2 > 0.f) ? v2 : 0.2f * v2;
            s += 0.5f * (v1 + v2);
        }
        s_attn[tid] = s * (1.f / NH);
    }
    __syncthreads();

    if (tid < NN) {
        float z[NN], m = -1e30f;
        #pragma unroll
        for (int j = 0; j < NN; ++j) { z[j] = s_attn[tid*NN + j] * 100.f; m = fmaxf(m, z[j]); }
        float ssum = 0.f;
        #pragma unroll
        for (int j = 0; j < NN; ++j) { z[j] = expf(z[j] - m); ssum += z[j]; }
        float inv = 1.f / ssum;
        float v[NN];
        #pragma unroll
        for (int j = 0; j < NN; ++j) v[j] = z[j] * inv;
        float m1 = -1.f, m2 = -1.f, m3 = -1.f;
        #pragma unroll
        for (int j = 0; j < NN; ++j) {
            float x = v[j];
            if (x > m1) { m3 = m2; m2 = m1; m1 = x; }
            else if (x > m2) { m3 = m2; m2 = x; }
            else if (x > m3) { m3 = x; }
        }
        #pragma unroll
        for (int j = 0; j < NN; ++j)
            s_Sp[tid*NN + j] = (v[j] >= m3) ? v[j] : 0.f;
    }
    __syncthreads();

    if (tid < NN*NN) {
        int i = tid / NN, j = tid % NN;
        s_adj[tid] = 0.5f * (s_Sp[i*NN + j] + s_Sp[j*NN + i]);
    }
    __syncthreads();

    if (tid < NN) {
        float d = 0.f;
        #pragma unroll
        for (int j = 0; j < NN; ++j) d += s_adj[tid*NN + j];
        s_dis[tid] = 1.f / sqrtf(d + 1e-6f);
    }
    __syncthreads();

    if (tid < NN*NN) {
        int i = tid / NN, j = tid % NN;
        s_op[tid] = s_dis[i] * s_adj[tid] * s_dis[j];
    }
    __syncthreads();

    if (tid < NN) {
        float c = 0.f;
        #pragma unroll
        for (int j = 0; j < NN; ++j)
            c = fmaf(s_op[tid*NN + j], s_op[j*NN + 0], c);
        g_c[b*NN + tid] = c;
    }
}

// ---------------- K3: node convs, f32x2 packed across co pairs ----------------
// grid (8 cog, 5 nodes, B). 256 threads: cg(0..3) x 64 spatial 4x4 tiles.
// Each thread: 4 co (2 co-pairs) x 16 px.
__global__ __launch_bounds__(256, 2)
void k3_nodes(const float* __restrict__ bg, const float* __restrict__ bb,
              const float* __restrict__ bm, const float* __restrict__ bv,
              const float* __restrict__ plifw)
{
    const int cog  = blockIdx.x;
    const int node = blockIdx.y + 1;
    const int b    = blockIdx.z;
    const int tid  = threadIdx.x;
    const int sp   = tid & 63;
    const int cg   = tid >> 6;
    const int hp0  = (sp >> 3) * 4, wp0 = (sp & 7) * 4;
    const int coBase = cog * 16 + cg * 4;

    __shared__ __align__(16) float s_in[4*34*36];   // 4 ci planes, padded
    __shared__ __align__(16) float s_w[4*9*16];     // [cc][k][co16]
    __shared__ float s_red[16];

    if (tid < 16) s_red[tid] = 0.f;

    u64 acc[2][16];
    #pragma unroll
    for (int up = 0; up < 2; ++up)
        #pragma unroll
        for (int p = 0; p < 16; ++p) acc[up][p] = 0ULL;

    const float4* inbase4 = (const float4*)(g_out0p + ((long long)b*COUT)*1224);
    const float*  wtbase  = g_wt + ((long long)(node-1)*COUT)*9*COUT + cog*16;

    for (int ci0 = 0; ci0 < COUT; ci0 += 4) {
        __syncthreads();
        // stage 4 input planes: contiguous float4 copy (no index math, no bounds)
        {
            const float4* src = inbase4 + (long long)ci0*306;
            float4* dst = (float4*)s_in;
            #pragma unroll 5
            for (int i = tid; i < 1224; i += 256) dst[i] = src[i];
        }
        // stage weights: [cc][k][16] from g_wt[n][ci0+cc][k][cog*16..+16]
        for (int i = tid; i < 144; i += 256) {
            int cc = i / 36, rem = i % 36;
            int k = rem >> 2, f = rem & 3;
            ((float4*)s_w)[i] = *(const float4*)(wtbase + ((long long)(ci0+cc)*9 + k)*COUT + f*4);
        }
        __syncthreads();

        #pragma unroll
        for (int cc = 0; cc < 4; ++cc) {
            const float* base_in = s_in + cc*1224 + hp0*36 + wp0;
            const float* base_w  = s_w + cc*144 + cg*4;
            #pragma unroll
            for (int up = 0; up < 2; ++up) {
                u64 wk[9];
                #pragma unroll
                for (int k = 0; k < 9; ++k)
                    wk[k] = *(const u64*)(base_w + k*16 + 2*up);
                #pragma unroll
                for (int r = 0; r < 6; ++r) {
                    const float* rp = base_in + r*36;
                    float4 a4 = *(const float4*)rp;
                    float2 a2 = *(const float2*)(rp + 4);
                    u64 xb[6];
                    xb[0] = bcast2(a4.x); xb[1] = bcast2(a4.y);
                    xb[2] = bcast2(a4.z); xb[3] = bcast2(a4.w);
                    xb[4] = bcast2(a2.x); xb[5] = bcast2(a2.y);
                    #pragma unroll
                    for (int kh = 0; kh < 3; ++kh) {
                        int ph = r - kh;
                        if (ph < 0 || ph > 3) continue;
                        #pragma unroll
                        for (int kw = 0; kw < 3; ++kw) {
                            u64 w2 = wk[kh*3 + kw];
                            #pragma unroll
                            for (int pw = 0; pw < 4; ++pw)
                                ffma2(acc[up][ph*4 + pw], xb[pw + kw], w2);
                        }
                    }
                }
            }
        }
    }

    // ---- epilogue: scale by c, bn, plif, spike, store spikes ----
    const float cscale = g_c[b*NN + node];
    const float sig = 1.f / (1.f + expf(-plifw[node]));

    float lsum[4] = {0.f, 0.f, 0.f, 0.f};
    #pragma unroll
    for (int up = 0; up < 2; ++up) {
        #pragma unroll
        for (int e = 0; e < 2; ++e) {
            int co = coBase + 2*up + e;
            int bi = (node - 1)*COUT + co;
            float inv = rsqrtf(bv[bi] + BN_EPS);
            float A = bg[bi] * inv;
            float Bc = bb[bi] - bm[bi] * A;
            long long vbase = (((long long)(node-1)*B_ + b)*COUT + co)*PLANE;
            long long sbase = (long long)(node-1)*OUTSZ + ((long long)(b*COUT + co))*PLANE;
            float ls = 0.f;
            #pragma unroll
            for (int p = 0; p < 16; ++p) {
                int ph = p >> 2, pw = p & 3;
                float lo, hi;
                unpack2(lo, hi, acc[up][p]);
                float y = (e == 0 ? lo : hi) * cscale;
                float ybn = y * A + Bc;
                int off = (hp0 + ph)*WPx + (wp0 + pw);
                float vp = g_vnodes[vbase + off];
                float v = vp + (ybn - vp)*sig;
                float sk = (v >= V_TH) ? 1.f : 0.f;
                g_vnodes[vbase + off] = v * (1.f - sk);
                g_spk[sbase + off] = sk;
                ls += sk;
            }
            lsum[2*up + e] = ls;
        }
    }

    #pragma unroll
    for (int l = 0; l < 4; ++l) {
        float v = lsum[l];
        #pragma unroll
        for (int off = 16; off > 0; off >>= 1)
            v += __shfl_down_sync(0xffffffffu, v, off);
        if ((tid & 31) == 0) atomicAdd(&s_red[cg*4 + l], v);
    }
    __syncthreads();
    if (tid < 16)
        g_nodemean[((node-1)*B_ + b)*COUT + cog*16 + tid] = s_red[tid] * (1.f/1024.f);
}

// ---------------- K5: combine node spikes into output (replaces atomics) ----------------
__global__ __launch_bounds__(256)
void k5_combine(const float* __restrict__ outw, float* __restrict__ out_t)
{
    int i = blockIdx.x * 256 + threadIdx.x;
    if (i >= OUTSZ) return;
    float v = out_t[i];   // node-0 contribution from K1
    #pragma unroll
    for (int n = 1; n < NN; ++n) {
        float ws = 1.f / (1.f + expf(-outw[n]));
        v = fmaf(ws, g_spk[(long long)(n-1)*OUTSZ + i], v);
    }
    out_t[i] = v;
}

// ---------------- K4: node feats -> trace update; zero mean0 ----------------
__global__ __launch_bounds__(128)
void k4_feats(const float* __restrict__ ft_w, const float* __restrict__ ft_b)
{
    const int b = blockIdx.x;
    const int tid = threadIdx.x;
    __shared__ float s_m[COUT];

    float f[NN];
    f[0] = g_feat0[b*COUT + tid];
    for (int n = 1; n < NN; ++n) {
        __syncthreads();
        s_m[tid] = g_nodemean[((n-1)*B_ + b)*COUT + tid];
        __syncthreads();
        float acc = ft_b[tid];
        #pragma unroll 4
        for (int c = 0; c < COUT; ++c)
            acc = fmaf(s_m[c], ft_w[tid*COUT + c], acc);
        f[n] = fmaxf(acc, 0.f);
    }
    #pragma unroll
    for (int n = 0; n < NN; ++n) {
        int idx = (b*NN + n)*COUT + tid;
        g_traces[idx] = 0.6f * g_traces[idx] + 0.4f * f[n];
    }
    g_mean0[b*COUT + tid] = 0.f;
}

// ---------------- host launch ----------------
extern "C" void kernel_launch(void* const* d_in, const int* in_sizes, int n_in,
                              void* d_out, int out_size)
{
    const float* x       = (const float*)d_in[0];
    const float* conv0_w = (const float*)d_in[1];
    const float* bn0_g   = (const float*)d_in[2];
    const float* bn0_b   = (const float*)d_in[3];
    const float* bn0_m   = (const float*)d_in[4];
    const float* bn0_v   = (const float*)d_in[5];
    const float* convs_w = (const float*)d_in[6];
    const float* bns_g   = (const float*)d_in[7];
    const float* bns_b   = (const float*)d_in[8];
    const float* bns_m   = (const float*)d_in[9];
    const float* bns_v   = (const float*)d_in[10];
    const float* plif_w  = (const float*)d_in[11];
    const float* ft_w    = (const float*)d_in[12];
    const float* ft_b    = (const float*)d_in[13];
    const float* gat_W   = (const float*)d_in[14];
    const float* gat_a   = (const float*)d_in[15];
    const float* out_w   = (const float*)d_in[16];
    float* out = (float*)d_out;

    k_init<<<2048, 256>>>();
    k_wreorg<<<((NN-1)*COUT*9*COUT + 255)/256, 256>>>(convs_w);

    for (int t = 0; t < T_; ++t) {
        const float* xt = x + (long long)t * B_ * CIN * HIMG * WIMG;
        float* out_t = out + (long long)t * OUTSZ;

        k1_conv0<<<dim3(32, B_), 256>>>(xt, conv0_w, bn0_g, bn0_b, bn0_m, bn0_v,
                                        plif_w, out_w, out_t);
        k2_graph<<<B_, 128>>>(ft_w, ft_b, gat_W, gat_a);
        k3_nodes<<<dim3(8, NN-1, B_), 256>>>(bns_g, bns_b, bns_m, bns_v, plif_w);
        k5_combine<<<(OUTSZ + 255)/256, 256>>>(out_w, out_t);
        k4_feats<<<B_, 128>>>(ft_w, ft_b);
    }
}